// round 7
// baseline (speedup 1.0000x reference)
#include <cuda_runtime.h>

// HyperbolicResidualAdd: every intermediate vector lies in span{x_row, y_row}.
// Warp-per-row, ZERO block barriers. Each warp independently:
//   1. loads its row once: x -> registers, y -> its private smem region,
//      reducing Gram (X2, Y2, XY) on the fly (butterfly-shuffle full-warp).
//   2. runs the scalar coefficient chain SIMT-redundantly with MUFU fast-math
//      (~150 instr -- cheap enough that dedup + barriers cost more than they save).
//   3. emits out = A*x(reg) + B*y(smem).
// Warps flow independently -> memory pipe never idles on a barrier bubble.

namespace {

constexpr int D    = 768;
constexpr int VEC  = D / 4;    // 192 float4 per row
constexpr int PL   = VEC / 32; // 6 float4 per lane
constexpr int WPB  = 8;        // warps (= rows) per block

constexpr float EPSN      = 1e-15f;
constexpr float BALL_EPS  = 1e-5f;
constexpr float TARG_MAX  = 15.0f;
constexpr float ATANH_MAX = 1.0f - 1e-7f;

struct V2 { float a, b; };

__device__ __forceinline__ float fast_tanh(float v) {
    float e = __expf(2.f * v);
    return __fdividef(e - 1.f, e + 1.f);
}
__device__ __forceinline__ float fast_atanh(float v) {
    return 0.5f * __logf(__fdividef(1.f + v, 1.f - v));
}
__device__ __forceinline__ float softplusf(float v) {
    return (v > 20.f) ? v : log1pf(expf(v));
}

__device__ __forceinline__ float nrm(V2 v, float X2, float Y2, float XY) {
    float n2 = v.a * v.a * X2 + 2.f * v.a * v.b * XY + v.b * v.b * Y2;
    return fmaxf(sqrtf(fmaxf(n2, 0.f)), EPSN);
}
__device__ __forceinline__ float dotc(V2 v, V2 w, float X2, float Y2, float XY) {
    return v.a * w.a * X2 + (v.a * w.b + v.b * w.a) * XY + v.b * w.b * Y2;
}
__device__ __forceinline__ V2 scl(V2 v, float f) { return V2{v.a * f, v.b * f}; }

__device__ __forceinline__ V2 post_clip(V2 v, float X2, float Y2, float XY, float sc) {
    float n = nrm(v, X2, Y2, XY);
    float maxn = (1.0f - BALL_EPS) / sc;
    return scl(v, fminf(1.f, __fdividef(maxn, n)));
}
__device__ __forceinline__ V2 pre_clip(V2 v, float X2, float Y2, float XY, float sc) {
    float n = nrm(v, X2, Y2, XY);
    float maxn = TARG_MAX / sc;
    return scl(v, fminf(1.f, __fdividef(maxn, n)));
}
__device__ __forceinline__ V2 expmap0(V2 v, float X2, float Y2, float XY, float sc) {
    float n = nrm(v, X2, Y2, XY);
    return scl(v, __fdividef(fast_tanh(sc * n), sc * n));
}
__device__ __forceinline__ V2 mob_smul(float r, V2 v, float X2, float Y2, float XY, float sc) {
    float n = nrm(v, X2, Y2, XY);
    float t = fast_atanh(fminf(sc * n, ATANH_MAX));
    return scl(v, __fdividef(fast_tanh(r * t), sc * n));
}
__device__ __forceinline__ V2 mob_add(V2 v, V2 w, float X2, float Y2, float XY, float c) {
    float v2 = dotc(v, v, X2, Y2, XY);
    float w2 = dotc(w, w, X2, Y2, XY);
    float vw = dotc(v, w, X2, Y2, XY);
    float cv = 1.f + 2.f * c * vw + c * w2;
    float cw = 1.f - c * v2;
    float den = fmaxf(1.f + 2.f * c * vw + c * c * v2 * w2, EPSN);
    float inv = __fdividef(1.f, den);
    return V2{(cv * v.a + cw * w.a) * inv, (cv * v.b + cw * w.b) * inv};
}

__global__ void __launch_bounds__(256)
hyperres_kernel(const float* __restrict__ x, const float* __restrict__ y,
                const float* __restrict__ p_curv, const float* __restrict__ p_graw,
                const float* __restrict__ p_gscale, const float* __restrict__ p_scenter,
                float* __restrict__ out, int rows)
{
    __shared__ float4 sy[WPB * VEC];   // 24 KB: y staged on-chip (per-warp private regions)

    int wid  = threadIdx.x >> 5;
    int lane = threadIdx.x & 31;
    int r    = blockIdx.x * WPB + wid;
    if (r >= rows) return;

    const float4* xr = reinterpret_cast<const float4*>(x) + (size_t)r * VEC + lane;
    const float4* yr = reinterpret_cast<const float4*>(y) + (size_t)r * VEC + lane;
    float4* syw = sy + wid * VEC + lane;

    // ---------- Load once: x -> regs, y -> smem; Gram reduce ----------
    float4 xv[PL], bv[PL];
#pragma unroll
    for (int i = 0; i < PL; i++) xv[i] = xr[i * 32];
#pragma unroll
    for (int i = 0; i < PL; i++) bv[i] = yr[i * 32];

    float X2 = 0.f, Y2 = 0.f, XY = 0.f;
#pragma unroll
    for (int i = 0; i < PL; i++) {
        float4 a = xv[i], b = bv[i];
        syw[i * 32] = b;   // same thread re-reads these addresses later: no sync needed
        X2 = fmaf(a.x, a.x, fmaf(a.y, a.y, fmaf(a.z, a.z, fmaf(a.w, a.w, X2))));
        Y2 = fmaf(b.x, b.x, fmaf(b.y, b.y, fmaf(b.z, b.z, fmaf(b.w, b.w, Y2))));
        XY = fmaf(a.x, b.x, fmaf(a.y, b.y, fmaf(a.z, b.z, fmaf(a.w, b.w, XY))));
    }
#pragma unroll
    for (int off = 16; off > 0; off >>= 1) {
        X2 += __shfl_xor_sync(0xffffffffu, X2, off);
        Y2 += __shfl_xor_sync(0xffffffffu, Y2, off);
        XY += __shfl_xor_sync(0xffffffffu, XY, off);
    }

    // ---------- Scalar chain (SIMT-redundant in-warp, fast-math) ----------
    float c  = softplusf(__ldg(p_curv));
    float sc = sqrtf(c);
    float s  = __fdividef(1.f, 1.f + __expf(-__ldg(p_scenter)));
    float g_max = 1.f + softplusf(__ldg(p_gscale));
    float gamma = g_max * fast_tanh(__ldg(p_graw));

    V2 xc{1.f, 0.f}, yc{0.f, 1.f};

    V2 hrx = post_clip(expmap0(pre_clip(xc, X2, Y2, XY, sc), X2, Y2, XY, sc), X2, Y2, XY, sc);
    V2 hry = post_clip(expmap0(pre_clip(yc, X2, Y2, XY, sc), X2, Y2, XY, sc), X2, Y2, XY, sc);

    V2 sx  = post_clip(mob_smul(s,       hrx, X2, Y2, XY, sc), X2, Y2, XY, sc);
    V2 syv = post_clip(mob_smul(1.f - s, hry, X2, Y2, XY, sc), X2, Y2, XY, sc);
    V2 p   = post_clip(mob_add(sx, syv, X2, Y2, XY, c), X2, Y2, XY, sc);

    V2 mp{-p.a, -p.b};
    V2 xp = post_clip(mob_add(mp, hrx, X2, Y2, XY, c), X2, Y2, XY, sc);
    V2 yp = post_clip(mob_add(mp, hry, X2, Y2, XY, c), X2, Y2, XY, sc);
    V2 ys = post_clip(mob_smul(gamma, yp, X2, Y2, XY, sc), X2, Y2, XY, sc);
    V2 hresp = post_clip(mob_add(xp, ys, X2, Y2, XY, c), X2, Y2, XY, sc);
    V2 hres  = mob_add(p, hresp, X2, Y2, XY, c);
    V2 rr    = post_clip(hres, X2, Y2, XY, sc);

    float nr = nrm(rr, X2, Y2, XY);
    float fl = __fdividef(fast_atanh(fminf(sc * nr, ATANH_MAX)), sc * nr);
    float A = fl * rr.a;
    float B = fl * rr.b;

    // ---------- Emit out = A*x(reg) + B*y(smem) ----------
    float4* orow = reinterpret_cast<float4*>(out) + (size_t)r * VEC + lane;
#pragma unroll
    for (int i = 0; i < PL; i++) {
        float4 a = xv[i];
        float4 b = syw[i * 32];
        float4 o;
        o.x = fmaf(A, a.x, B * b.x);
        o.y = fmaf(A, a.y, B * b.y);
        o.z = fmaf(A, a.z, B * b.z);
        o.w = fmaf(A, a.w, B * b.w);
        orow[i * 32] = o;
    }
}

} // namespace

extern "C" void kernel_launch(void* const* d_in, const int* in_sizes, int n_in,
                              void* d_out, int out_size)
{
    const float* x       = (const float*)d_in[0];
    const float* y       = (const float*)d_in[1];
    const float* curv    = (const float*)d_in[2];
    const float* graw    = (const float*)d_in[3];
    const float* gscale  = (const float*)d_in[4];
    const float* scenter = (const float*)d_in[5];

    int rows = in_sizes[0] / D;            // 64*577 = 36928
    int blocks = (rows + WPB - 1) / WPB;   // 4616

    hyperres_kernel<<<blocks, 256>>>(x, y, curv, graw, gscale, scenter,
                                     (float*)d_out, rows);
}

// round 8
// speedup vs baseline: 1.0808x; 1.0808x over previous
#include <cuda_runtime.h>
#include <cuda_pipeline.h>

// HyperbolicResidualAdd: every intermediate vector lies in span{x_row, y_row}.
// Block = 8 warps, warp-per-row (R6 structure: measured best).
// Phase 1: cp.async y -> smem (no register round-trip), x -> regs via __ldcs
//          (streaming, evict-first), Gram (X2,Y2,XY) reduced in-warp.
// Phase 2: warp 0 runs all 8 scalar chains lane-parallel, MUFU fast-math.
// Phase 3: emit out = A*x(reg) + B*y(smem) with __stcs streaming stores.
// launch_bounds(256,5): regs<=51 -> 5 blocks/SM (smem 24KB*5=120KB fits).

namespace {

constexpr int D    = 768;
constexpr int VEC  = D / 4;    // 192 float4 per row
constexpr int PL   = VEC / 32; // 6 float4 per lane
constexpr int WPB  = 8;        // warps (= rows) per block

constexpr float EPSN      = 1e-15f;
constexpr float BALL_EPS  = 1e-5f;
constexpr float TARG_MAX  = 15.0f;
constexpr float ATANH_MAX = 1.0f - 1e-7f;

struct V2 { float a, b; };

__device__ __forceinline__ float fast_tanh(float v) {
    float e = __expf(2.f * v);
    return __fdividef(e - 1.f, e + 1.f);
}
__device__ __forceinline__ float fast_atanh(float v) {
    return 0.5f * __logf(__fdividef(1.f + v, 1.f - v));
}
__device__ __forceinline__ float softplusf(float v) {
    return (v > 20.f) ? v : log1pf(expf(v));
}

__device__ __forceinline__ float nrm(V2 v, float X2, float Y2, float XY) {
    float n2 = v.a * v.a * X2 + 2.f * v.a * v.b * XY + v.b * v.b * Y2;
    return fmaxf(sqrtf(fmaxf(n2, 0.f)), EPSN);
}
__device__ __forceinline__ float dotc(V2 v, V2 w, float X2, float Y2, float XY) {
    return v.a * w.a * X2 + (v.a * w.b + v.b * w.a) * XY + v.b * w.b * Y2;
}
__device__ __forceinline__ V2 scl(V2 v, float f) { return V2{v.a * f, v.b * f}; }

__device__ __forceinline__ V2 post_clip(V2 v, float X2, float Y2, float XY, float sc) {
    float n = nrm(v, X2, Y2, XY);
    float maxn = (1.0f - BALL_EPS) / sc;
    return scl(v, fminf(1.f, __fdividef(maxn, n)));
}
__device__ __forceinline__ V2 pre_clip(V2 v, float X2, float Y2, float XY, float sc) {
    float n = nrm(v, X2, Y2, XY);
    float maxn = TARG_MAX / sc;
    return scl(v, fminf(1.f, __fdividef(maxn, n)));
}
__device__ __forceinline__ V2 expmap0(V2 v, float X2, float Y2, float XY, float sc) {
    float n = nrm(v, X2, Y2, XY);
    return scl(v, __fdividef(fast_tanh(sc * n), sc * n));
}
__device__ __forceinline__ V2 mob_smul(float r, V2 v, float X2, float Y2, float XY, float sc) {
    float n = nrm(v, X2, Y2, XY);
    float t = fast_atanh(fminf(sc * n, ATANH_MAX));
    return scl(v, __fdividef(fast_tanh(r * t), sc * n));
}
__device__ __forceinline__ V2 mob_add(V2 v, V2 w, float X2, float Y2, float XY, float c) {
    float v2 = dotc(v, v, X2, Y2, XY);
    float w2 = dotc(w, w, X2, Y2, XY);
    float vw = dotc(v, w, X2, Y2, XY);
    float cv = 1.f + 2.f * c * vw + c * w2;
    float cw = 1.f - c * v2;
    float den = fmaxf(1.f + 2.f * c * vw + c * c * v2 * w2, EPSN);
    float inv = __fdividef(1.f, den);
    return V2{(cv * v.a + cw * w.a) * inv, (cv * v.b + cw * w.b) * inv};
}

__global__ void __launch_bounds__(256, 5)
hyperres_kernel(const float* __restrict__ x, const float* __restrict__ y,
                const float* __restrict__ p_curv, const float* __restrict__ p_graw,
                const float* __restrict__ p_gscale, const float* __restrict__ p_scenter,
                float* __restrict__ out, int rows)
{
    __shared__ float4 sy[WPB * VEC];                 // 24 KB: y staged via cp.async
    __shared__ float sX2[WPB], sY2[WPB], sXY[WPB], sA[WPB], sB[WPB];

    int wid  = threadIdx.x >> 5;
    int lane = threadIdx.x & 31;
    int r    = blockIdx.x * WPB + wid;
    bool valid = (r < rows);

    const float4* xr = reinterpret_cast<const float4*>(x) + (size_t)r * VEC + lane;
    const float4* yr = reinterpret_cast<const float4*>(y) + (size_t)r * VEC + lane;
    float4* syw = sy + wid * VEC + lane;

    float4 xv[PL];

    // ---------- Phase 1: cp.async y -> smem; x -> regs (__ldcs); Gram ----------
    if (valid) {
#pragma unroll
        for (int i = 0; i < PL; i++)
            __pipeline_memcpy_async(&syw[i * 32], &yr[i * 32], sizeof(float4));
        __pipeline_commit();

        float X2 = 0.f;
#pragma unroll
        for (int i = 0; i < PL; i++) {
            float4 a = __ldcs(&xr[i * 32]);
            xv[i] = a;
            X2 = fmaf(a.x, a.x, fmaf(a.y, a.y, fmaf(a.z, a.z, fmaf(a.w, a.w, X2))));
        }

        __pipeline_wait_prior(0);

        float Y2 = 0.f, XY = 0.f;
#pragma unroll
        for (int i = 0; i < PL; i++) {
            float4 a = xv[i];
            float4 b = syw[i * 32];
            Y2 = fmaf(b.x, b.x, fmaf(b.y, b.y, fmaf(b.z, b.z, fmaf(b.w, b.w, Y2))));
            XY = fmaf(a.x, b.x, fmaf(a.y, b.y, fmaf(a.z, b.z, fmaf(a.w, b.w, XY))));
        }
#pragma unroll
        for (int off = 16; off > 0; off >>= 1) {
            X2 += __shfl_xor_sync(0xffffffffu, X2, off);
            Y2 += __shfl_xor_sync(0xffffffffu, Y2, off);
            XY += __shfl_xor_sync(0xffffffffu, XY, off);
        }
        if (lane == 0) { sX2[wid] = X2; sY2[wid] = Y2; sXY[wid] = XY; }
    }
    __syncthreads();

    // ---------- Phase 2: warp 0 runs 8 chains, one per lane ----------
    if (wid == 0) {
        bool act = (lane < WPB) && (blockIdx.x * WPB + lane < rows);
        float X2 = act ? sX2[lane] : 1.f;
        float Y2 = act ? sY2[lane] : 1.f;
        float XY = act ? sXY[lane] : 0.f;

        float c  = softplusf(__ldg(p_curv));
        float sc = sqrtf(c);
        float s  = __fdividef(1.f, 1.f + __expf(-__ldg(p_scenter)));
        float g_max = 1.f + softplusf(__ldg(p_gscale));
        float gamma = g_max * fast_tanh(__ldg(p_graw));

        V2 xc{1.f, 0.f}, yc{0.f, 1.f};

        V2 hrx = post_clip(expmap0(pre_clip(xc, X2, Y2, XY, sc), X2, Y2, XY, sc), X2, Y2, XY, sc);
        V2 hry = post_clip(expmap0(pre_clip(yc, X2, Y2, XY, sc), X2, Y2, XY, sc), X2, Y2, XY, sc);

        V2 sx  = post_clip(mob_smul(s,       hrx, X2, Y2, XY, sc), X2, Y2, XY, sc);
        V2 syv = post_clip(mob_smul(1.f - s, hry, X2, Y2, XY, sc), X2, Y2, XY, sc);
        V2 p   = post_clip(mob_add(sx, syv, X2, Y2, XY, c), X2, Y2, XY, sc);

        V2 mp{-p.a, -p.b};
        V2 xp = post_clip(mob_add(mp, hrx, X2, Y2, XY, c), X2, Y2, XY, sc);
        V2 yp = post_clip(mob_add(mp, hry, X2, Y2, XY, c), X2, Y2, XY, sc);
        V2 ys = post_clip(mob_smul(gamma, yp, X2, Y2, XY, sc), X2, Y2, XY, sc);
        V2 hresp = post_clip(mob_add(xp, ys, X2, Y2, XY, c), X2, Y2, XY, sc);
        V2 hres  = mob_add(p, hresp, X2, Y2, XY, c);
        V2 rr    = post_clip(hres, X2, Y2, XY, sc);

        float nr = nrm(rr, X2, Y2, XY);
        float fl = __fdividef(fast_atanh(fminf(sc * nr, ATANH_MAX)), sc * nr);
        if (lane < WPB) {
            sA[lane] = fl * rr.a;
            sB[lane] = fl * rr.b;
        }
    }
    __syncthreads();

    // ---------- Phase 3: emit out = A*x(reg) + B*y(smem), streaming stores ----------
    if (valid) {
        float A = sA[wid], B = sB[wid];
        float4* orow = reinterpret_cast<float4*>(out) + (size_t)r * VEC + lane;
#pragma unroll
        for (int i = 0; i < PL; i++) {
            float4 a = xv[i];
            float4 b = syw[i * 32];
            float4 o;
            o.x = fmaf(A, a.x, B * b.x);
            o.y = fmaf(A, a.y, B * b.y);
            o.z = fmaf(A, a.z, B * b.z);
            o.w = fmaf(A, a.w, B * b.w);
            __stcs(&orow[i * 32], o);
        }
    }
}

} // namespace

extern "C" void kernel_launch(void* const* d_in, const int* in_sizes, int n_in,
                              void* d_out, int out_size)
{
    const float* x       = (const float*)d_in[0];
    const float* y       = (const float*)d_in[1];
    const float* curv    = (const float*)d_in[2];
    const float* graw    = (const float*)d_in[3];
    const float* gscale  = (const float*)d_in[4];
    const float* scenter = (const float*)d_in[5];

    int rows = in_sizes[0] / D;            // 64*577 = 36928
    int blocks = (rows + WPB - 1) / WPB;   // 4616

    hyperres_kernel<<<blocks, 256>>>(x, y, curv, graw, gscale, scenter,
                                     (float*)d_out, rows);
}